// round 6
// baseline (speedup 1.0000x reference)
#include <cuda_runtime.h>
#include <cuda_bf16.h>
#include <cstdint>

// Inputs (metadata order):
//   d_in[0] features  : float32 [100000*128]
//   d_in[1] neigh_ids : int32   [1600000]   (JAX x64 disabled -> int32!)
//   d_in[2] row_ids   : int32   [1600000]   (SORTED ascending)
//   d_in[3] num_segments (scalar, ignored; derived from out_size)
// Output: float32 [num_rows * 128]

#define D_FEAT 128
#define MAX_ROWS 50008

// Scratch: segment offsets (no device allocation allowed -> __device__ global)
__device__ int g_offsets[MAX_ROWS + 1];

// Kernel 1: g_offsets[r] = lower_bound(row_ids, E, r); g_offsets[R] = E
__global__ void compute_offsets_kernel(const int* __restrict__ row_ids,
                                       int E, int R) {
    int r = blockIdx.x * blockDim.x + threadIdx.x;
    if (r > R) return;
    if (r == R) { g_offsets[R] = E; return; }
    int lo = 0, hi = E;
    while (lo < hi) {
        int mid = (lo + hi) >> 1;
        if (__ldg(&row_ids[mid]) < r) lo = mid + 1;
        else                          hi = mid;
    }
    g_offsets[r] = lo;
}

// Kernel 2: one warp per output row; lane handles 4 features (float4).
// 4-wide manual unroll over edges for memory-level parallelism.
__global__ void mean_agg_kernel(const float* __restrict__ features,
                                const int* __restrict__ neigh_ids,
                                float* __restrict__ out, int R) {
    const int warps_per_block = blockDim.x >> 5;
    const int warp_id = threadIdx.x >> 5;
    const int lane    = threadIdx.x & 31;
    const int row     = blockIdx.x * warps_per_block + warp_id;
    if (row >= R) return;

    const int start = g_offsets[row];
    const int end   = g_offsets[row + 1];

    const float4* __restrict__ feat4 = (const float4*)features;

    float4 acc = make_float4(0.f, 0.f, 0.f, 0.f);

    int e = start;
    // 4-wide unroll: 4 independent id loads, then 4 independent float4 loads
    for (; e + 4 <= end; e += 4) {
        int n0 = __ldg(&neigh_ids[e + 0]);
        int n1 = __ldg(&neigh_ids[e + 1]);
        int n2 = __ldg(&neigh_ids[e + 2]);
        int n3 = __ldg(&neigh_ids[e + 3]);
        float4 v0 = __ldg(&feat4[(size_t)n0 * 32 + lane]);
        float4 v1 = __ldg(&feat4[(size_t)n1 * 32 + lane]);
        float4 v2 = __ldg(&feat4[(size_t)n2 * 32 + lane]);
        float4 v3 = __ldg(&feat4[(size_t)n3 * 32 + lane]);
        acc.x += v0.x; acc.y += v0.y; acc.z += v0.z; acc.w += v0.w;
        acc.x += v1.x; acc.y += v1.y; acc.z += v1.z; acc.w += v1.w;
        acc.x += v2.x; acc.y += v2.y; acc.z += v2.z; acc.w += v2.w;
        acc.x += v3.x; acc.y += v3.y; acc.z += v3.z; acc.w += v3.w;
    }
    for (; e < end; ++e) {
        int n = __ldg(&neigh_ids[e]);
        float4 v = __ldg(&feat4[(size_t)n * 32 + lane]);
        acc.x += v.x; acc.y += v.y; acc.z += v.z; acc.w += v.w;
    }

    float cnt = (float)(end - start);
    float inv = 1.0f / fmaxf(cnt, 1.0f);
    acc.x *= inv; acc.y *= inv; acc.z *= inv; acc.w *= inv;

    float4* out4 = (float4*)out;
    out4[(size_t)row * 32 + lane] = acc;
}

extern "C" void kernel_launch(void* const* d_in, const int* in_sizes, int n_in,
                              void* d_out, int out_size) {
    const float* features  = (const float*)d_in[0];
    const int*   neigh_ids = (const int*)d_in[1];
    const int*   row_ids   = (const int*)d_in[2];
    float* out = (float*)d_out;

    const int E = in_sizes[1];
    const int R = out_size / D_FEAT;

    // Kernel 1: segment boundaries via binary search over sorted row_ids
    {
        int threads = 256;
        int blocks  = (R + 1 + threads - 1) / threads;
        compute_offsets_kernel<<<blocks, threads>>>(row_ids, E, R);
    }
    // Kernel 2: warp-per-row mean aggregation
    {
        int threads = 256;                 // 8 warps = 8 rows per block
        int warps_per_block = threads / 32;
        int blocks = (R + warps_per_block - 1) / warps_per_block;
        mean_agg_kernel<<<blocks, threads>>>(features, neigh_ids, out, R);
    }
}

// round 7
// speedup vs baseline: 1.1708x; 1.1708x over previous
#include <cuda_runtime.h>
#include <cuda_bf16.h>
#include <cstdint>

// Inputs (metadata order):
//   d_in[0] features  : float32 [100000*128]
//   d_in[1] neigh_ids : int32   [1600000]
//   d_in[2] row_ids   : int32   [1600000]   (SORTED ascending, ~uniform)
//   d_in[3] num_segments (scalar, ignored; derived from out_size)
// Output: float32 [num_rows * 128]

#define D_FEAT 128
#define MAX_ROWS 50008

__device__ int g_offsets[MAX_ROWS + 1];

// Kernel 1: g_offsets[r] = lower_bound(row_ids, E, r); g_offsets[R] = E
// row_ids is sorted ~uniform, so lower_bound(r) ~= r*E/R. Try a +/-8K window
// first (2 validation probes), fall back to full range if invalid.
__global__ void compute_offsets_kernel(const int* __restrict__ row_ids,
                                       int E, int R) {
    int r = blockIdx.x * blockDim.x + threadIdx.x;
    if (r > R) return;
    if (r == R) { g_offsets[R] = E; return; }

    const int W = 8192;
    int est = (int)(((long long)r * (long long)E) / (long long)R);
    int wlo = est - W; if (wlo < 0) wlo = 0;
    int whi = est + W; if (whi > E) whi = E;

    // p (= first idx with row_ids[p] >= r) lies in [wlo, whi] iff:
    bool below_ok = (wlo == 0) || (__ldg(&row_ids[wlo - 1]) < r);
    bool above_ok = (whi == E) || (__ldg(&row_ids[whi]) >= r);

    int lo, hi;
    if (below_ok && above_ok) { lo = wlo; hi = whi; }
    else                      { lo = 0;   hi = E;   }

    while (lo < hi) {
        int mid = (lo + hi) >> 1;
        if (__ldg(&row_ids[mid]) < r) lo = mid + 1;
        else                          hi = mid;
    }
    g_offsets[r] = lo;
}

// Kernel 2: one warp per output row; lane = 4 features (float4).
// 8-wide edge unroll -> 8 independent gathers in flight per warp.
// 64-thread blocks (2 warps) for fine-grained HW load balancing.
__global__ void __launch_bounds__(64)
mean_agg_kernel(const float* __restrict__ features,
                const int* __restrict__ neigh_ids,
                float* __restrict__ out, int R) {
    const int warp_id = threadIdx.x >> 5;
    const int lane    = threadIdx.x & 31;
    const int row     = blockIdx.x * 2 + warp_id;
    if (row >= R) return;

    const int start = g_offsets[row];
    const int end   = g_offsets[row + 1];

    const float4* __restrict__ feat4 = (const float4*)features;

    float4 acc = make_float4(0.f, 0.f, 0.f, 0.f);

    int e = start;
    // 8-wide unroll: 8 independent id loads then 8 independent float4 gathers
    for (; e + 8 <= end; e += 8) {
        int n0 = __ldg(&neigh_ids[e + 0]);
        int n1 = __ldg(&neigh_ids[e + 1]);
        int n2 = __ldg(&neigh_ids[e + 2]);
        int n3 = __ldg(&neigh_ids[e + 3]);
        int n4 = __ldg(&neigh_ids[e + 4]);
        int n5 = __ldg(&neigh_ids[e + 5]);
        int n6 = __ldg(&neigh_ids[e + 6]);
        int n7 = __ldg(&neigh_ids[e + 7]);
        float4 v0 = __ldg(&feat4[(size_t)n0 * 32 + lane]);
        float4 v1 = __ldg(&feat4[(size_t)n1 * 32 + lane]);
        float4 v2 = __ldg(&feat4[(size_t)n2 * 32 + lane]);
        float4 v3 = __ldg(&feat4[(size_t)n3 * 32 + lane]);
        float4 v4 = __ldg(&feat4[(size_t)n4 * 32 + lane]);
        float4 v5 = __ldg(&feat4[(size_t)n5 * 32 + lane]);
        float4 v6 = __ldg(&feat4[(size_t)n6 * 32 + lane]);
        float4 v7 = __ldg(&feat4[(size_t)n7 * 32 + lane]);
        // pairwise add tree (shortens live ranges slightly)
        v0.x += v1.x; v0.y += v1.y; v0.z += v1.z; v0.w += v1.w;
        v2.x += v3.x; v2.y += v3.y; v2.z += v3.z; v2.w += v3.w;
        v4.x += v5.x; v4.y += v5.y; v4.z += v5.z; v4.w += v5.w;
        v6.x += v7.x; v6.y += v7.y; v6.z += v7.z; v6.w += v7.w;
        v0.x += v2.x; v0.y += v2.y; v0.z += v2.z; v0.w += v2.w;
        v4.x += v6.x; v4.y += v6.y; v4.z += v6.z; v4.w += v6.w;
        acc.x += v0.x + v4.x;
        acc.y += v0.y + v4.y;
        acc.z += v0.z + v4.z;
        acc.w += v0.w + v4.w;
    }
    for (; e + 4 <= end; e += 4) {
        int n0 = __ldg(&neigh_ids[e + 0]);
        int n1 = __ldg(&neigh_ids[e + 1]);
        int n2 = __ldg(&neigh_ids[e + 2]);
        int n3 = __ldg(&neigh_ids[e + 3]);
        float4 v0 = __ldg(&feat4[(size_t)n0 * 32 + lane]);
        float4 v1 = __ldg(&feat4[(size_t)n1 * 32 + lane]);
        float4 v2 = __ldg(&feat4[(size_t)n2 * 32 + lane]);
        float4 v3 = __ldg(&feat4[(size_t)n3 * 32 + lane]);
        acc.x += v0.x; acc.y += v0.y; acc.z += v0.z; acc.w += v0.w;
        acc.x += v1.x; acc.y += v1.y; acc.z += v1.z; acc.w += v1.w;
        acc.x += v2.x; acc.y += v2.y; acc.z += v2.z; acc.w += v2.w;
        acc.x += v3.x; acc.y += v3.y; acc.z += v3.z; acc.w += v3.w;
    }
    for (; e < end; ++e) {
        int n = __ldg(&neigh_ids[e]);
        float4 v = __ldg(&feat4[(size_t)n * 32 + lane]);
        acc.x += v.x; acc.y += v.y; acc.z += v.z; acc.w += v.w;
    }

    float cnt = (float)(end - start);
    float inv = 1.0f / fmaxf(cnt, 1.0f);
    acc.x *= inv; acc.y *= inv; acc.z *= inv; acc.w *= inv;

    float4* out4 = (float4*)out;
    out4[(size_t)row * 32 + lane] = acc;
}

extern "C" void kernel_launch(void* const* d_in, const int* in_sizes, int n_in,
                              void* d_out, int out_size) {
    const float* features  = (const float*)d_in[0];
    const int*   neigh_ids = (const int*)d_in[1];
    const int*   row_ids   = (const int*)d_in[2];
    float* out = (float*)d_out;

    const int E = in_sizes[1];
    const int R = out_size / D_FEAT;

    {
        int threads = 256;
        int blocks  = (R + 1 + threads - 1) / threads;
        compute_offsets_kernel<<<blocks, threads>>>(row_ids, E, R);
    }
    {
        int threads = 64;                   // 2 warps = 2 rows per block
        int blocks  = (R + 1) / 2;
        mean_agg_kernel<<<blocks, threads>>>(features, neigh_ids, out, R);
    }
}